// round 16
// baseline (speedup 1.0000x reference)
#include <cuda_runtime.h>
#include <cstdint>

#define NKEYS 50000
#define DDIM  64
#define NA    8
#define NB    256
#define KNN   50
#define DELTA 0.001f

// GEMM tiling
#define BQ   64
#define BK   256
#define KTP  258   // padded row length for transposed K (floats)

// Candidate buffer
#define CAP   8192        // per (a,b); expected ~600, 13x headroom
#define SEEDN 4096        // seed sample size (keys 0..4095)

// Output offsets (float32 elements)
#define OFF_MAX   0
#define OFF_ACT   256
#define OFF_VALS  512
#define OFF_IDX   2560
#define OFF_SCORE 104960

// padding key: value +inf, max idx -> sorts after every real key
#define PADKEY ((0xFF800000ull << 32) | 0xFFFFFFFFull)

// Scratch (module-load allocation, allowed)
__device__ unsigned long long g_cand[(size_t)NA * NB * CAP];  // 134 MB
__device__ int   g_cnt[NA * NB];
__device__ float g_thr0[NA * NB];
__device__ float g_ksq[NA * NKEYS];
__device__ float g_qsq[NB];

// ---------------------------------------------------------------------------
// Reference-replica reduction (LLVM AArch64 NEON: VF=4, IC=2, faddp horiz).
// DO NOT TOUCH — bit-exactness verified in R8/R9/R15.
// ---------------------------------------------------------------------------
__device__ __forceinline__ float reduce64_sq(const float* __restrict__ x) {
    float p0x=0.f,p0y=0.f,p0z=0.f,p0w=0.f;
    float p1x=0.f,p1y=0.f,p1z=0.f,p1w=0.f;
    #pragma unroll
    for (int i = 0; i < 8; i++) {
        float4 a = *(const float4*)(x + 8 * i);
        float4 b = *(const float4*)(x + 8 * i + 4);
        p0x = __fmaf_rn(a.x, a.x, p0x);
        p0y = __fmaf_rn(a.y, a.y, p0y);
        p0z = __fmaf_rn(a.z, a.z, p0z);
        p0w = __fmaf_rn(a.w, a.w, p0w);
        p1x = __fmaf_rn(b.x, b.x, p1x);
        p1y = __fmaf_rn(b.y, b.y, p1y);
        p1z = __fmaf_rn(b.z, b.z, p1z);
        p1w = __fmaf_rn(b.w, b.w, p1w);
    }
    float a0 = __fadd_rn(p0x, p1x);
    float a1 = __fadd_rn(p0y, p1y);
    float a2 = __fadd_rn(p0z, p1z);
    float a3 = __fadd_rn(p0w, p1w);
    return __fadd_rn(__fadd_rn(a0, a1), __fadd_rn(a2, a3));
}

__device__ __forceinline__ float reduce64_diff_sq(const float* __restrict__ q,
                                                  const float* __restrict__ k) {
    float p0[4] = {0.f,0.f,0.f,0.f};
    float p1[4] = {0.f,0.f,0.f,0.f};
    #pragma unroll
    for (int i = 0; i < 8; i++) {
        #pragma unroll
        for (int j = 0; j < 4; j++) {
            float d0 = __fsub_rn(q[8*i + j],     k[8*i + j]);
            float d1 = __fsub_rn(q[8*i + 4 + j], k[8*i + 4 + j]);
            p0[j] = __fmaf_rn(d0, d0, p0[j]);
            p1[j] = __fmaf_rn(d1, d1, p1[j]);
        }
    }
    float a0 = __fadd_rn(p0[0], p1[0]);
    float a1 = __fadd_rn(p0[1], p1[1]);
    float a2 = __fadd_rn(p0[2], p1[2]);
    float a3 = __fadd_rn(p0[3], p1[3]);
    return __fadd_rn(__fadd_rn(a0, a1), __fadd_rn(a2, a3));
}

// ---------------------------------------------------------------------------
__global__ void ksq_kernel(const float* __restrict__ keys) {
    int kk = blockIdx.x * 256 + threadIdx.x;
    if (kk >= NA * NKEYS) return;
    g_ksq[kk] = reduce64_sq(keys + (size_t)kk * DDIM);
}

__global__ void qsq_kernel(const float* __restrict__ q) {
    int b = threadIdx.x;
    g_qsq[b] = reduce64_sq(q + (size_t)b * DDIM);
}

__global__ void zero_kernel() {
    int i = blockIdx.x * 256 + threadIdx.x;
    if (i < NA * NB) g_cnt[i] = 0;
}

// ---------------------------------------------------------------------------
// Seed: per (a,b), replica-exact d2 of keys 0..SEEDN-1; per-thread min of 16,
// thr0 = 50th smallest of the 256 mins. Each of those 50 mins is a distinct
// element <= thr0, so thr0 >= global 50th -> filter is lossless.
// Scalar fmaf chain == each f32x2 lane chain (same rounding).
// ---------------------------------------------------------------------------
__global__ void __launch_bounds__(256)
seed_kernel(const float* __restrict__ query, const float* __restrict__ keys) {
    __shared__ float s_mins[256];
    __shared__ float qv[DDIM];
    int t = threadIdx.x;
    int b = blockIdx.x, a = blockIdx.y;
    if (t < DDIM) qv[t] = query[(size_t)b * DDIM + t];
    __syncthreads();
    float qs = g_qsq[b];
    float mymin = 3.4e38f;
    #pragma unroll 2
    for (int r = 0; r < SEEDN / 256; r++) {
        int n = t + 256 * r;
        const float* kp = keys + ((size_t)a * NKEYS + n) * DDIM;
        float acc = 0.f;
        #pragma unroll
        for (int k = 0; k < DDIM; k++) acc = __fmaf_rn(qv[k], __ldg(kp + k), acc);
        float d2 = __fsub_rn(__fadd_rn(qs, g_ksq[a * NKEYS + n]), __fmul_rn(2.0f, acc));
        mymin = fminf(mymin, d2);
    }
    s_mins[t] = mymin;
    __syncthreads();
    for (int k = 2; k <= 256; k <<= 1) {
        for (int j = k >> 1; j; j >>= 1) {
            int i = t, l = i ^ j;
            if (l > i) {
                float x = s_mins[i], y = s_mins[l];
                bool up = ((i & k) == 0);
                if ((x > y) == up) { s_mins[i] = y; s_mins[l] = x; }
            }
            __syncthreads();
        }
    }
    if (t == 0) g_thr0[a * NB + b] = s_mins[KNN - 1];
}

// ---------------------------------------------------------------------------
// Distance GEMM, reference-replica rounding; epilogue filters against thr0
// and appends packed (d2,idx) candidates (no d2 array at all).
// ---------------------------------------------------------------------------
__global__ void __launch_bounds__(256, 2)
gemm_kernel(const float* __restrict__ query, const float* __restrict__ keys) {
    extern __shared__ char smraw[];
    unsigned long long* Qp = (unsigned long long*)smraw;          // [BQ][DDIM] (q,q) pairs
    float* Kt    = (float*)(smraw + BQ * DDIM * 8);               // [DDIM][KTP]
    float* s_ks  = (float*)(smraw + BQ * DDIM * 8 + DDIM * KTP * 4);   // [BK]
    float* s_thr = s_ks + BK;                                     // [BQ]

    int t = threadIdx.x;
    int nt = blockIdx.x, bt = blockIdx.y, a = blockIdx.z;
    int n0 = nt * BK;

    #pragma unroll
    for (int i = 0; i < 4; i++) {
        int f4 = t + 256 * i;
        int qi = f4 >> 4, dc = f4 & 15;
        float4 v = *(const float4*)(query + (size_t)(bt * BQ + qi) * DDIM + dc * 4);
        unsigned long long* dst = Qp + qi * DDIM + dc * 4;
        unsigned ux = __float_as_uint(v.x), uy = __float_as_uint(v.y);
        unsigned uz = __float_as_uint(v.z), uw = __float_as_uint(v.w);
        dst[0] = ((unsigned long long)ux << 32) | ux;
        dst[1] = ((unsigned long long)uy << 32) | uy;
        dst[2] = ((unsigned long long)uz << 32) | uz;
        dst[3] = ((unsigned long long)uw << 32) | uw;
    }
    const float* kb = keys + (size_t)a * NKEYS * DDIM;
    #pragma unroll
    for (int i = 0; i < 16; i++) {
        int f4 = t + 256 * i;
        int ki = f4 >> 4, dc = f4 & 15;
        int n = n0 + ki;
        float4 v = make_float4(0.f, 0.f, 0.f, 0.f);
        if (n < NKEYS) v = *(const float4*)(kb + (size_t)n * DDIM + dc * 4);
        Kt[(dc * 4 + 0) * KTP + ki] = v.x;
        Kt[(dc * 4 + 1) * KTP + ki] = v.y;
        Kt[(dc * 4 + 2) * KTP + ki] = v.z;
        Kt[(dc * 4 + 3) * KTP + ki] = v.w;
    }
    {
        int n = n0 + t;
        s_ks[t] = (n < NKEYS) ? g_ksq[a * NKEYS + n] : 0.f;
        if (t < BQ) s_thr[t] = g_thr0[a * NB + bt * BQ + t];
    }
    __syncthreads();

    int tx = t & 31, ty = t >> 5;
    unsigned lmlt = (1u << tx) - 1u;
    unsigned long long acc[8][4];
    #pragma unroll
    for (int i = 0; i < 8; i++)
        #pragma unroll
        for (int j = 0; j < 4; j++) acc[i][j] = 0ull;

    const unsigned long long* qb = Qp + (ty * 8) * DDIM;

    #pragma unroll 4
    for (int k = 0; k < DDIM; k++) {
        unsigned long long k2[4];
        const float* kr = Kt + k * KTP;
        #pragma unroll
        for (int j = 0; j < 4; j++)
            k2[j] = *(const unsigned long long*)(kr + 2 * (tx + 32 * j));
        unsigned long long q2[8];
        #pragma unroll
        for (int i = 0; i < 8; i++)
            q2[i] = qb[i * DDIM + k];
        #pragma unroll
        for (int i = 0; i < 8; i++)
            #pragma unroll
            for (int j = 0; j < 4; j++)
                asm("fma.rn.f32x2 %0, %1, %2, %0;"
                    : "+l"(acc[i][j]) : "l"(q2[i]), "l"(k2[j]));
    }

    // epilogue: filtered warp-aggregated append (replica-exact d2 unchanged)
    #pragma unroll
    for (int i = 0; i < 8; i++) {
        int qloc = ty * 8 + i;
        int b = bt * BQ + qloc;
        float qs  = g_qsq[b];
        float thr = s_thr[qloc];
        unsigned long long* cb = g_cand + (size_t)(a * NB + b) * CAP;
        int* cp = g_cnt + (a * NB + b);
        #pragma unroll
        for (int j = 0; j < 4; j++) {
            int nl = 2 * (tx + 32 * j);
            unsigned long long v = acc[i][j];
            #pragma unroll
            for (int c = 0; c < 2; c++) {
                unsigned du = (c == 0) ? (unsigned)(v & 0xffffffffull)
                                       : (unsigned)(v >> 32);
                float dot = __uint_as_float(du);
                float ks  = s_ks[nl + c];
                float d2  = __fsub_rn(__fadd_rn(qs, ks), __fmul_rn(2.0f, dot));
                int n = n0 + nl + c;
                bool pass = (n < NKEYS) && (d2 <= thr);
                unsigned m = __ballot_sync(0xffffffffu, pass);
                if (m) {
                    int leader = __ffs(m) - 1;
                    int base = 0;
                    if (tx == leader) base = atomicAdd(cp, __popc(m));
                    base = __shfl_sync(0xffffffffu, base, leader);
                    if (pass) {
                        int pos = base + __popc(m & lmlt);
                        if (pos < CAP) {
                            unsigned u = __float_as_uint(d2);
                            u = (u & 0x80000000u) ? ~u : (u | 0x80000000u);
                            cb[pos] = ((unsigned long long)u << 32) | (unsigned)n;
                        }
                    }
                }
            }
        }
    }
}

// ---------------------------------------------------------------------------
// Warp-scope compaction (R13-proven): sort staging (<=64), keep lowest 64 of
// (top U stg). Exact (value,idx) key order; cnt warp-uniform.
// ---------------------------------------------------------------------------
__device__ __forceinline__ void warp_compact(unsigned long long* top,
                                             unsigned long long* stg,
                                             int cnt, int lane) {
    #pragma unroll
    for (int r = 0; r < 2; r++) { int i = lane + 32*r; if (i >= cnt) stg[i] = PADKEY; }
    __syncwarp();
    for (int k = 2; k <= 64; k <<= 1) {
        for (int j = k >> 1; j; j >>= 1) {
            #pragma unroll
            for (int r = 0; r < 2; r++) {
                int i = lane + 32*r, l = i ^ j;
                if (l > i) {
                    unsigned long long x = stg[i], y = stg[l];
                    bool up = ((i & k) == 0);
                    if ((x > y) == up) { stg[i] = y; stg[l] = x; }
                }
            }
            __syncwarp();
        }
    }
    #pragma unroll
    for (int r = 0; r < 2; r++) {
        int i = lane + 32*r;
        unsigned long long x = top[i], y = stg[63 - i];
        top[i] = x < y ? x : y;
    }
    __syncwarp();
    for (int j = 32; j; j >>= 1) {
        #pragma unroll
        for (int r = 0; r < 2; r++) {
            int i = lane + 32*r, l = i ^ j;
            if (l > i) {
                unsigned long long x = top[i], y = top[l];
                if (x > y) { top[i] = y; top[l] = x; }
            }
        }
        __syncwarp();
    }
}

// ---------------------------------------------------------------------------
// Select: merge ~600 candidates per (a,b). 8 warps compact disjoint stripes
// (warp-sync only), one barrier, warp 0 tournament-merges + outputs.
// ---------------------------------------------------------------------------
__global__ void __launch_bounds__(256)
select_kernel(const float* __restrict__ query, const float* __restrict__ keys,
              const float* __restrict__ vals, float* __restrict__ out) {
    __shared__ unsigned long long s_top[8][64];
    __shared__ unsigned long long s_stg[8][64];
    __shared__ float qv[DDIM];
    __shared__ float s_w[64], s_wv[64];

    int t = threadIdx.x, w = t >> 5, lane = t & 31;
    int b = blockIdx.x, a = blockIdx.y;
    int p = a * NB + b;

    if (t < DDIM) qv[t] = query[(size_t)b * DDIM + t];
    #pragma unroll
    for (int r = 0; r < 2; r++) s_top[w][lane + 32 * r] = PADKEY;
    __syncwarp();

    int cnt = min(g_cnt[p], CAP);
    const unsigned long long* cb = g_cand + (size_t)p * CAP;

    // warp w handles stripe [lo, hi)
    int per = (cnt + 7) / 8;
    int lo = w * per;
    int hi = min(lo + per, cnt);
    for (int s = lo; s < hi; s += 64) {
        int m = min(64, hi - s);
        #pragma unroll
        for (int r = 0; r < 2; r++) {
            int i = lane + 32 * r;
            if (i < m) s_stg[w][i] = cb[s + i];
        }
        __syncwarp();
        warp_compact(s_top[w], s_stg[w], m, lane);
    }
    __syncthreads();

    if (w == 0) {
        // tournament-merge 8 sorted lists -> exact global top-64
        for (int s = 1; s < 8; s++) {
            #pragma unroll
            for (int r = 0; r < 2; r++) {
                int i = lane + 32 * r;
                unsigned long long x = s_top[0][i], y = s_top[s][63 - i];
                s_top[0][i] = x < y ? x : y;
            }
            __syncwarp();
            for (int j = 32; j; j >>= 1) {
                #pragma unroll
                for (int r = 0; r < 2; r++) {
                    int i = lane + 32 * r, l = i ^ j;
                    if (l > i) {
                        unsigned long long x = s_top[0][i], y = s_top[0][l];
                        if (x > y) { s_top[0][i] = y; s_top[0][l] = x; }
                    }
                }
                __syncwarp();
            }
        }

        // outputs: replica-exact recompute (reduce64_diff_sq)
        #pragma unroll
        for (int r = 0; r < 2; r++) {
            int ni = lane + 32 * r;
            if (ni < KNN) {
                int idx = (int)(s_top[0][ni] & 0xffffffffull);
                const float* kp = keys + ((size_t)a * NKEYS + idx) * DDIM;
                float dist = reduce64_diff_sq(qv, kp);
                float wt = 1.0f / (dist + DELTA);
                s_w[ni]  = wt;
                s_wv[ni] = wt * vals[(size_t)a * NKEYS + idx];
                out[OFF_IDX   + (b * NA + a) * KNN + ni] = (float)idx;
                out[OFF_SCORE + (b * NA + a) * KNN + ni] = dist;
            }
        }
        __syncwarp();
        if (lane == 0) {
            float sw = 0.f, swv = 0.f;
            for (int i = 0; i < KNN; i++) { sw += s_w[i]; swv += s_wv[i]; }
            out[OFF_VALS + b * NA + a] = swv / sw;
        }
    }
}

// ---------------------------------------------------------------------------
__global__ void finalize_kernel(float* __restrict__ out) {
    int b = threadIdx.x;
    if (b < NB) {
        float best = out[OFF_VALS + b * NA];
        int arg = 0;
        #pragma unroll
        for (int a = 1; a < NA; a++) {
            float v = out[OFF_VALS + b * NA + a];
            if (v > best) { best = v; arg = a; }
        }
        out[OFF_MAX + b] = best;
        out[OFF_ACT + b] = (float)arg;
    }
}

// ---------------------------------------------------------------------------
extern "C" void kernel_launch(void* const* d_in, const int* in_sizes, int n_in,
                              void* d_out, int out_size) {
    const float* query = (const float*)d_in[0];
    const float* keys  = (const float*)d_in[1];
    const float* vals  = (const float*)d_in[2];
    float* out = (float*)d_out;

    const int gemm_smem = BQ * DDIM * 8 + DDIM * KTP * 4 + (BK + BQ) * 4;  // 100096 B
    cudaFuncSetAttribute(gemm_kernel,
                         cudaFuncAttributeMaxDynamicSharedMemorySize, gemm_smem);

    ksq_kernel<<<(NA * NKEYS + 255) / 256, 256>>>(keys);
    qsq_kernel<<<1, 256>>>(query);
    zero_kernel<<<(NA * NB + 255) / 256, 256>>>();

    dim3 gseed(NB, NA);
    seed_kernel<<<gseed, 256>>>(query, keys);

    dim3 gg((NKEYS + BK - 1) / BK, NB / BQ, NA);
    gemm_kernel<<<gg, 256, gemm_smem>>>(query, keys);

    dim3 gs(NB, NA);
    select_kernel<<<gs, 256>>>(query, keys, vals, out);

    finalize_kernel<<<1, 256>>>(out);
}

// round 17
// speedup vs baseline: 3.3127x; 3.3127x over previous
#include <cuda_runtime.h>
#include <cstdint>

#define NKEYS 50000
#define DDIM  64
#define NA    8
#define NB    256
#define KNN   50
#define DELTA 0.001f

// GEMM tiling
#define BQ   64
#define BK   256
#define KTP  258   // padded row length for transposed K (floats)

// Candidate buffer / seed
#define CAP    8192       // per (a,b); expected ~600, 13x headroom
#define SEEDN  4096       // seed sample size (keys 0..4095)
#define SEEDNT (SEEDN / BK)   // 16 n-tiles

// Output offsets (float32 elements)
#define OFF_MAX   0
#define OFF_ACT   256
#define OFF_VALS  512
#define OFF_IDX   2560
#define OFF_SCORE 104960

// padding key: value +inf, max idx -> sorts after every real key
#define PADKEY ((0xFF800000ull << 32) | 0xFFFFFFFFull)

// Scratch (module-load allocation, allowed)
__device__ unsigned long long g_cand[(size_t)NA * NB * CAP];  // 134 MB
__device__ float g_seed[(size_t)NA * NB * SEEDN];             // 33.5 MB
__device__ int   g_cnt[NA * NB];
__device__ float g_thr0[NA * NB];
__device__ float g_ksq[NA * NKEYS];
__device__ float g_qsq[NB];

// ---------------------------------------------------------------------------
// Reference-replica reduction (LLVM AArch64 NEON: VF=4, IC=2, faddp horiz).
// DO NOT TOUCH — bit-exactness verified in R8/R9/R15.
// ---------------------------------------------------------------------------
__device__ __forceinline__ float reduce64_sq(const float* __restrict__ x) {
    float p0x=0.f,p0y=0.f,p0z=0.f,p0w=0.f;
    float p1x=0.f,p1y=0.f,p1z=0.f,p1w=0.f;
    #pragma unroll
    for (int i = 0; i < 8; i++) {
        float4 a = *(const float4*)(x + 8 * i);
        float4 b = *(const float4*)(x + 8 * i + 4);
        p0x = __fmaf_rn(a.x, a.x, p0x);
        p0y = __fmaf_rn(a.y, a.y, p0y);
        p0z = __fmaf_rn(a.z, a.z, p0z);
        p0w = __fmaf_rn(a.w, a.w, p0w);
        p1x = __fmaf_rn(b.x, b.x, p1x);
        p1y = __fmaf_rn(b.y, b.y, p1y);
        p1z = __fmaf_rn(b.z, b.z, p1z);
        p1w = __fmaf_rn(b.w, b.w, p1w);
    }
    float a0 = __fadd_rn(p0x, p1x);
    float a1 = __fadd_rn(p0y, p1y);
    float a2 = __fadd_rn(p0z, p1z);
    float a3 = __fadd_rn(p0w, p1w);
    return __fadd_rn(__fadd_rn(a0, a1), __fadd_rn(a2, a3));
}

__device__ __forceinline__ float reduce64_diff_sq(const float* __restrict__ q,
                                                  const float* __restrict__ k) {
    float p0[4] = {0.f,0.f,0.f,0.f};
    float p1[4] = {0.f,0.f,0.f,0.f};
    #pragma unroll
    for (int i = 0; i < 8; i++) {
        #pragma unroll
        for (int j = 0; j < 4; j++) {
            float d0 = __fsub_rn(q[8*i + j],     k[8*i + j]);
            float d1 = __fsub_rn(q[8*i + 4 + j], k[8*i + 4 + j]);
            p0[j] = __fmaf_rn(d0, d0, p0[j]);
            p1[j] = __fmaf_rn(d1, d1, p1[j]);
        }
    }
    float a0 = __fadd_rn(p0[0], p1[0]);
    float a1 = __fadd_rn(p0[1], p1[1]);
    float a2 = __fadd_rn(p0[2], p1[2]);
    float a3 = __fadd_rn(p0[3], p1[3]);
    return __fadd_rn(__fadd_rn(a0, a1), __fadd_rn(a2, a3));
}

// ---------------------------------------------------------------------------
__global__ void ksq_kernel(const float* __restrict__ keys) {
    int kk = blockIdx.x * 256 + threadIdx.x;
    if (kk >= NA * NKEYS) return;
    g_ksq[kk] = reduce64_sq(keys + (size_t)kk * DDIM);
}

__global__ void qsq_kernel(const float* __restrict__ q) {
    int b = threadIdx.x;
    g_qsq[b] = reduce64_sq(q + (size_t)b * DDIM);
}

__global__ void zero_kernel() {
    int i = blockIdx.x * 256 + threadIdx.x;
    if (i < NA * NB) g_cnt[i] = 0;
}

// ---------------------------------------------------------------------------
// Shared GEMM tile stage + mainloop (identical replica arithmetic everywhere).
// ---------------------------------------------------------------------------
__device__ __forceinline__ void gemm_stage_and_mainloop(
    const float* __restrict__ query, const float* __restrict__ keys,
    char* smraw, int t, int n0, int nlimit, int bt, int a,
    unsigned long long (&acc)[8][4])
{
    unsigned long long* Qp = (unsigned long long*)smraw;          // [BQ][DDIM] (q,q)
    float* Kt = (float*)(smraw + BQ * DDIM * 8);                  // [DDIM][KTP]

    #pragma unroll
    for (int i = 0; i < 4; i++) {
        int f4 = t + 256 * i;
        int qi = f4 >> 4, dc = f4 & 15;
        float4 v = *(const float4*)(query + (size_t)(bt * BQ + qi) * DDIM + dc * 4);
        unsigned long long* dst = Qp + qi * DDIM + dc * 4;
        unsigned ux = __float_as_uint(v.x), uy = __float_as_uint(v.y);
        unsigned uz = __float_as_uint(v.z), uw = __float_as_uint(v.w);
        dst[0] = ((unsigned long long)ux << 32) | ux;
        dst[1] = ((unsigned long long)uy << 32) | uy;
        dst[2] = ((unsigned long long)uz << 32) | uz;
        dst[3] = ((unsigned long long)uw << 32) | uw;
    }
    const float* kb = keys + (size_t)a * NKEYS * DDIM;
    #pragma unroll
    for (int i = 0; i < 16; i++) {
        int f4 = t + 256 * i;
        int ki = f4 >> 4, dc = f4 & 15;
        int n = n0 + ki;
        float4 v = make_float4(0.f, 0.f, 0.f, 0.f);
        if (n < nlimit) v = *(const float4*)(kb + (size_t)n * DDIM + dc * 4);
        Kt[(dc * 4 + 0) * KTP + ki] = v.x;
        Kt[(dc * 4 + 1) * KTP + ki] = v.y;
        Kt[(dc * 4 + 2) * KTP + ki] = v.z;
        Kt[(dc * 4 + 3) * KTP + ki] = v.w;
    }
    __syncthreads();

    int tx = t & 31, ty = t >> 5;
    #pragma unroll
    for (int i = 0; i < 8; i++)
        #pragma unroll
        for (int j = 0; j < 4; j++) acc[i][j] = 0ull;

    const unsigned long long* qb = Qp + (ty * 8) * DDIM;

    #pragma unroll 4
    for (int k = 0; k < DDIM; k++) {
        unsigned long long k2[4];
        const float* kr = Kt + k * KTP;
        #pragma unroll
        for (int j = 0; j < 4; j++)
            k2[j] = *(const unsigned long long*)(kr + 2 * (tx + 32 * j));
        unsigned long long q2[8];
        #pragma unroll
        for (int i = 0; i < 8; i++)
            q2[i] = qb[i * DDIM + k];
        #pragma unroll
        for (int i = 0; i < 8; i++)
            #pragma unroll
            for (int j = 0; j < 4; j++)
                asm("fma.rn.f32x2 %0, %1, %2, %0;"
                    : "+l"(acc[i][j]) : "l"(q2[i]), "l"(k2[j]));
    }
}

// ---------------------------------------------------------------------------
// Seed GEMM: replica-exact d2 for keys [0, SEEDN) -> g_seed. Bit-identical
// to the main GEMM's d2 (same staged tiles, same lane chains, same combine).
// ---------------------------------------------------------------------------
__global__ void __launch_bounds__(256, 2)
seed_gemm_kernel(const float* __restrict__ query, const float* __restrict__ keys) {
    extern __shared__ char smraw[];
    int t = threadIdx.x;
    int nt = blockIdx.x, bt = blockIdx.y, a = blockIdx.z;
    int n0 = nt * BK;

    unsigned long long acc[8][4];
    gemm_stage_and_mainloop(query, keys, smraw, t, n0, NKEYS, bt, a, acc);

    int tx = t & 31, ty = t >> 5;
    #pragma unroll
    for (int j = 0; j < 4; j++) {
        int n = n0 + 2 * (tx + 32 * j);
        float2 ks2 = *(const float2*)(g_ksq + a * NKEYS + n);
        #pragma unroll
        for (int i = 0; i < 8; i++) {
            int b = bt * BQ + ty * 8 + i;
            float qs = g_qsq[b];
            unsigned long long v = acc[i][j];
            float lo = __uint_as_float((unsigned)(v & 0xffffffffull));
            float hi = __uint_as_float((unsigned)(v >> 32));
            float d0 = __fsub_rn(__fadd_rn(qs, ks2.x), __fmul_rn(2.0f, lo));
            float d1 = __fsub_rn(__fadd_rn(qs, ks2.y), __fmul_rn(2.0f, hi));
            float* orow = g_seed + (size_t)(a * NB + b) * SEEDN;
            __stcs((float2*)(orow + n), make_float2(d0, d1));
        }
    }
}

// ---------------------------------------------------------------------------
// thr0 per (a,b): 50th smallest of 256 per-thread mins (16 distinct keys
// each) over the replica-exact seed d2. Lossless: 50 distinct elements are
// <= thr0, so thr0 >= the full-set 50th smallest.
// ---------------------------------------------------------------------------
__global__ void __launch_bounds__(256)
thr_kernel() {
    __shared__ float s_mins[256];
    int t = threadIdx.x;
    int b = blockIdx.x, a = blockIdx.y;
    const float4* row = (const float4*)(g_seed + (size_t)(a * NB + b) * SEEDN);
    float m = 3.4e38f;
    #pragma unroll
    for (int r = 0; r < SEEDN / 1024; r++) {
        float4 v = __ldcs(&row[t + 256 * r]);
        m = fminf(m, fminf(fminf(v.x, v.y), fminf(v.z, v.w)));
    }
    s_mins[t] = m;
    __syncthreads();
    for (int k = 2; k <= 256; k <<= 1) {
        for (int j = k >> 1; j; j >>= 1) {
            int i = t, l = i ^ j;
            if (l > i) {
                float x = s_mins[i], y = s_mins[l];
                bool up = ((i & k) == 0);
                if ((x > y) == up) { s_mins[i] = y; s_mins[l] = x; }
            }
            __syncthreads();
        }
    }
    if (t == 0) g_thr0[a * NB + b] = s_mins[KNN - 1];
}

// ---------------------------------------------------------------------------
// Main GEMM: replica d2 + filter-append of packed (d2,idx) candidates.
// ---------------------------------------------------------------------------
__global__ void __launch_bounds__(256, 2)
gemm_kernel(const float* __restrict__ query, const float* __restrict__ keys) {
    extern __shared__ char smraw[];
    float* s_ks  = (float*)(smraw + BQ * DDIM * 8 + DDIM * KTP * 4);   // [BK]
    float* s_thr = s_ks + BK;                                          // [BQ]

    int t = threadIdx.x;
    int nt = blockIdx.x, bt = blockIdx.y, a = blockIdx.z;
    int n0 = nt * BK;

    {
        int n = n0 + t;
        s_ks[t] = (n < NKEYS) ? g_ksq[a * NKEYS + n] : 0.f;
        if (t < BQ) s_thr[t] = g_thr0[a * NB + bt * BQ + t];
    }

    unsigned long long acc[8][4];
    gemm_stage_and_mainloop(query, keys, smraw, t, n0, NKEYS, bt, a, acc);

    int tx = t & 31, ty = t >> 5;
    unsigned lmlt = (1u << tx) - 1u;

    // epilogue: filtered warp-aggregated append (replica-exact d2 unchanged)
    #pragma unroll
    for (int i = 0; i < 8; i++) {
        int qloc = ty * 8 + i;
        int b = bt * BQ + qloc;
        float qs  = g_qsq[b];
        float thr = s_thr[qloc];
        unsigned long long* cb = g_cand + (size_t)(a * NB + b) * CAP;
        int* cp = g_cnt + (a * NB + b);
        #pragma unroll
        for (int j = 0; j < 4; j++) {
            int nl = 2 * (tx + 32 * j);
            unsigned long long v = acc[i][j];
            #pragma unroll
            for (int c = 0; c < 2; c++) {
                unsigned du = (c == 0) ? (unsigned)(v & 0xffffffffull)
                                       : (unsigned)(v >> 32);
                float dot = __uint_as_float(du);
                float ks  = s_ks[nl + c];
                float d2  = __fsub_rn(__fadd_rn(qs, ks), __fmul_rn(2.0f, dot));
                int n = n0 + nl + c;
                bool pass = (n < NKEYS) && (d2 <= thr);
                unsigned m = __ballot_sync(0xffffffffu, pass);
                if (m) {
                    int leader = __ffs(m) - 1;
                    int base = 0;
                    if (tx == leader) base = atomicAdd(cp, __popc(m));
                    base = __shfl_sync(0xffffffffu, base, leader);
                    if (pass) {
                        int pos = base + __popc(m & lmlt);
                        if (pos < CAP) {
                            unsigned u = __float_as_uint(d2);
                            u = (u & 0x80000000u) ? ~u : (u | 0x80000000u);
                            cb[pos] = ((unsigned long long)u << 32) | (unsigned)n;
                        }
                    }
                }
            }
        }
    }
}

// ---------------------------------------------------------------------------
// Warp-scope compaction (validated): sort staging (<=64), keep lowest 64 of
// (top U stg). Exact (value,idx) key order; cnt warp-uniform.
// ---------------------------------------------------------------------------
__device__ __forceinline__ void warp_compact(unsigned long long* top,
                                             unsigned long long* stg,
                                             int cnt, int lane) {
    #pragma unroll
    for (int r = 0; r < 2; r++) { int i = lane + 32*r; if (i >= cnt) stg[i] = PADKEY; }
    __syncwarp();
    for (int k = 2; k <= 64; k <<= 1) {
        for (int j = k >> 1; j; j >>= 1) {
            #pragma unroll
            for (int r = 0; r < 2; r++) {
                int i = lane + 32*r, l = i ^ j;
                if (l > i) {
                    unsigned long long x = stg[i], y = stg[l];
                    bool up = ((i & k) == 0);
                    if ((x > y) == up) { stg[i] = y; stg[l] = x; }
                }
            }
            __syncwarp();
        }
    }
    #pragma unroll
    for (int r = 0; r < 2; r++) {
        int i = lane + 32*r;
        unsigned long long x = top[i], y = stg[63 - i];
        top[i] = x < y ? x : y;
    }
    __syncwarp();
    for (int j = 32; j; j >>= 1) {
        #pragma unroll
        for (int r = 0; r < 2; r++) {
            int i = lane + 32*r, l = i ^ j;
            if (l > i) {
                unsigned long long x = top[i], y = top[l];
                if (x > y) { top[i] = y; top[l] = x; }
            }
        }
        __syncwarp();
    }
}

// ---------------------------------------------------------------------------
// Select: merge ~600 candidates per (a,b). 8 warps compact disjoint stripes
// (warp-sync only), one barrier, warp 0 tournament-merges + outputs.
// ---------------------------------------------------------------------------
__global__ void __launch_bounds__(256)
select_kernel(const float* __restrict__ query, const float* __restrict__ keys,
              const float* __restrict__ vals, float* __restrict__ out) {
    __shared__ unsigned long long s_top[8][64];
    __shared__ unsigned long long s_stg[8][64];
    __shared__ float qv[DDIM];
    __shared__ float s_w[64], s_wv[64];

    int t = threadIdx.x, w = t >> 5, lane = t & 31;
    int b = blockIdx.x, a = blockIdx.y;
    int p = a * NB + b;

    if (t < DDIM) qv[t] = query[(size_t)b * DDIM + t];
    #pragma unroll
    for (int r = 0; r < 2; r++) s_top[w][lane + 32 * r] = PADKEY;
    __syncwarp();

    int cnt = min(g_cnt[p], CAP);
    const unsigned long long* cb = g_cand + (size_t)p * CAP;

    int per = (cnt + 7) / 8;
    int lo = w * per;
    int hi = min(lo + per, cnt);
    for (int s = lo; s < hi; s += 64) {
        int m = min(64, hi - s);
        #pragma unroll
        for (int r = 0; r < 2; r++) {
            int i = lane + 32 * r;
            if (i < m) s_stg[w][i] = cb[s + i];
        }
        __syncwarp();
        warp_compact(s_top[w], s_stg[w], m, lane);
    }
    __syncthreads();

    if (w == 0) {
        for (int s = 1; s < 8; s++) {
            #pragma unroll
            for (int r = 0; r < 2; r++) {
                int i = lane + 32 * r;
                unsigned long long x = s_top[0][i], y = s_top[s][63 - i];
                s_top[0][i] = x < y ? x : y;
            }
            __syncwarp();
            for (int j = 32; j; j >>= 1) {
                #pragma unroll
                for (int r = 0; r < 2; r++) {
                    int i = lane + 32 * r, l = i ^ j;
                    if (l > i) {
                        unsigned long long x = s_top[0][i], y = s_top[0][l];
                        if (x > y) { s_top[0][i] = y; s_top[0][l] = x; }
                    }
                }
                __syncwarp();
            }
        }

        // outputs: replica-exact recompute (reduce64_diff_sq)
        #pragma unroll
        for (int r = 0; r < 2; r++) {
            int ni = lane + 32 * r;
            if (ni < KNN) {
                int idx = (int)(s_top[0][ni] & 0xffffffffull);
                const float* kp = keys + ((size_t)a * NKEYS + idx) * DDIM;
                float dist = reduce64_diff_sq(qv, kp);
                float wt = 1.0f / (dist + DELTA);
                s_w[ni]  = wt;
                s_wv[ni] = wt * vals[(size_t)a * NKEYS + idx];
                out[OFF_IDX   + (b * NA + a) * KNN + ni] = (float)idx;
                out[OFF_SCORE + (b * NA + a) * KNN + ni] = dist;
            }
        }
        __syncwarp();
        if (lane == 0) {
            float sw = 0.f, swv = 0.f;
            for (int i = 0; i < KNN; i++) { sw += s_w[i]; swv += s_wv[i]; }
            out[OFF_VALS + b * NA + a] = swv / sw;
        }
    }
}

// ---------------------------------------------------------------------------
__global__ void finalize_kernel(float* __restrict__ out) {
    int b = threadIdx.x;
    if (b < NB) {
        float best = out[OFF_VALS + b * NA];
        int arg = 0;
        #pragma unroll
        for (int a = 1; a < NA; a++) {
            float v = out[OFF_VALS + b * NA + a];
            if (v > best) { best = v; arg = a; }
        }
        out[OFF_MAX + b] = best;
        out[OFF_ACT + b] = (float)arg;
    }
}

// ---------------------------------------------------------------------------
extern "C" void kernel_launch(void* const* d_in, const int* in_sizes, int n_in,
                              void* d_out, int out_size) {
    const float* query = (const float*)d_in[0];
    const float* keys  = (const float*)d_in[1];
    const float* vals  = (const float*)d_in[2];
    float* out = (float*)d_out;

    const int gemm_smem = BQ * DDIM * 8 + DDIM * KTP * 4 + (BK + BQ) * 4;  // 100096 B
    cudaFuncSetAttribute(gemm_kernel,
                         cudaFuncAttributeMaxDynamicSharedMemorySize, gemm_smem);
    cudaFuncSetAttribute(seed_gemm_kernel,
                         cudaFuncAttributeMaxDynamicSharedMemorySize, gemm_smem);

    ksq_kernel<<<(NA * NKEYS + 255) / 256, 256>>>(keys);
    qsq_kernel<<<1, 256>>>(query);
    zero_kernel<<<(NA * NB + 255) / 256, 256>>>();

    dim3 gseed(SEEDNT, NB / BQ, NA);
    seed_gemm_kernel<<<gseed, 256, gemm_smem>>>(query, keys);

    dim3 gthr(NB, NA);
    thr_kernel<<<gthr, 256>>>();

    dim3 gg((NKEYS + BK - 1) / BK, NB / BQ, NA);
    gemm_kernel<<<gg, 256, gemm_smem>>>(query, keys);

    dim3 gs(NB, NA);
    select_kernel<<<gs, 256>>>(query, keys, vals, out);

    finalize_kernel<<<1, 256>>>(out);
}